// round 7
// baseline (speedup 1.0000x reference)
#include <cuda_runtime.h>

// RegL1Loss: out[b] = sum_{p,d} valid * |preds[b, idx] - val| / num_people[b]
// B=32, P=64, D=34, L=1048576. gts packed as [...,3] = (val, idx_as_float, flag).
//
// Grid = B * 8 chunks = 256 CTAs: spreads the 69632 random gather lines across
// all 148 SMs' L1tex queues (prev version: 32 CTAs -> 32 SMs -> ~2176
// wavefronts/SM; now ~470/SM). Each chunk = 272 elements = exactly 8 persons,
// so person-validity is CTA-local. Cross-CTA combine via device scratch +
// atomics + last-arrival ticket; finisher divides and resets scratch to zero
// so every graph replay starts from a clean state.

#define B 32
#define P 64
#define D 34
#define PD (P * D)        // 2176
#define L 1048576
#define CHUNKS 8
#define EPC (PD / CHUNKS) // 272 elements per CTA
#define PPC (EPC / D)     // 8 persons per CTA
#define ACT (EPC / 4)     // 68 loader threads, 4 elements each
#define TPC 96            // 3 warps

__device__ float    g_sum[B];     // zero-init at load; finisher resets
__device__ int      g_cnt[B];
__device__ unsigned g_ticket[B];

__global__ __launch_bounds__(TPC) void regl1_kernel(
    const float* __restrict__ preds,
    const float* __restrict__ gts,
    float* __restrict__ out)
{
    const int cta   = blockIdx.x;
    const int b     = cta >> 3;
    const int chunk = cta & 7;
    const int tid   = threadIdx.x;

    __shared__ int   pv[PPC];
    __shared__ float wsum[TPC / 32];

    if (tid < PPC) pv[tid] = 0;
    __syncthreads();

    float acc = 0.0f;
    if (tid < ACT) {
        // 12 consecutive floats per thread = 3 float4 loads (16B-aligned:
        // base = (b*2176 + chunk*272)*12B, thread offset = 48*tid B).
        const float4* __restrict__ g4 =
            (const float4*)(gts + ((size_t)b * PD + chunk * EPC) * 3) +
            (size_t)tid * 3;
        const float* __restrict__ pr = preds + (size_t)b * L;

        float4 a0 = g4[0];
        float4 a1 = g4[1];
        float4 a2 = g4[2];

        float vals[4] = { a0.x, a0.w, a1.z, a2.y };
        float fidx[4] = { a0.y, a1.x, a1.w, a2.z };
        float flag[4] = { a0.z, a1.y, a2.x, a2.w };

        bool  v[4];
        float gat[4];
        #pragma unroll
        for (int i = 0; i < 4; i++) {
            v[i]   = flag[i] > 0.0f;
            gat[i] = v[i] ? __ldg(pr + (int)fidx[i]) : 0.0f;  // independent gathers
        }

        const int e0 = tid * 4;   // element index within chunk
        #pragma unroll
        for (int i = 0; i < 4; i++) {
            if (v[i]) {
                acc += fabsf(gat[i] - vals[i]);
                pv[(e0 + i) / D] = 1;   // benign race: all writers store 1
            }
        }
    }

    // intra-CTA reduce (3 warps)
    #pragma unroll
    for (int off = 16; off > 0; off >>= 1)
        acc += __shfl_xor_sync(0xFFFFFFFFu, acc, off);

    const int wid = tid >> 5;
    const int lid = tid & 31;
    if (lid == 0) wsum[wid] = acc;
    __syncthreads();

    if (tid == 0) {
        float total = wsum[0] + wsum[1] + wsum[2];
        int cnt = 0;
        #pragma unroll
        for (int p = 0; p < PPC; p++) cnt += pv[p];

        atomicAdd(&g_sum[b], total);
        atomicAdd(&g_cnt[b], cnt);
        __threadfence();
        unsigned t = atomicAdd(&g_ticket[b], 1u);
        if (t == CHUNKS - 1) {
            // all 8 chunks' adds happened-before their ticket incs (fenced),
            // and we observed all tickets -> reads below see the full sums.
            float s = *(volatile float*)&g_sum[b];
            int   c = *(volatile int*)&g_cnt[b];
            out[b] = s / (float)c;
            // reset scratch for the next graph replay
            *(volatile float*)&g_sum[b]    = 0.0f;
            *(volatile int*)&g_cnt[b]      = 0;
            *(volatile unsigned*)&g_ticket[b] = 0u;
        }
    }
}

extern "C" void kernel_launch(void* const* d_in, const int* in_sizes, int n_in,
                              void* d_out, int out_size)
{
    const float* preds = (const float*)d_in[0];
    const float* gts   = (const float*)d_in[1];
    float* out = (float*)d_out;
    regl1_kernel<<<B * CHUNKS, TPC>>>(preds, gts, out);
}

// round 10
// speedup vs baseline: 1.1184x; 1.1184x over previous
#include <cuda_runtime.h>
#include <cstdint>

// RegL1Loss: out[b] = sum_{p,d} valid * |preds[b, idx] - val| / num_people[b]
// B=32, P=64, D=34, L=1048576. gts packed as [...,3] = (val, idx_as_float, flag).
//
// One 4-CTA cluster per batch image (grid=128). Each CTA handles 544 elements
// = exactly 16 persons (person-aligned -> validity is CTA-local). Partial
// (sum, cnt) combined through rank-0's SMEM via mapa + st.shared::cluster and
// a single cluster.sync — no global atomics, no scratch reset, fully
// deterministic and graph-replay-safe.

#define B 32
#define P 64
#define D 34
#define PD (P * D)          // 2176
#define L 1048576
#define CSIZE 4             // CTAs per cluster (per batch)
#define EPC (PD / CSIZE)    // 544 elements per CTA
#define PPC (EPC / D)       // 16 persons per CTA
#define LOADERS (EPC / 4)   // 136 loader threads, 4 elements each
#define TPC 160             // 5 warps
#define NW (TPC / 32)

__global__ __launch_bounds__(TPC) __cluster_dims__(CSIZE, 1, 1)
void regl1_kernel(const float* __restrict__ preds,
                  const float* __restrict__ gts,
                  float* __restrict__ out)
{
    const int cta   = blockIdx.x;
    const int b     = cta / CSIZE;
    const int chunk = cta % CSIZE;
    const int tid   = threadIdx.x;

    __shared__ int   pv[PPC];
    __shared__ float wsum[NW];
    __shared__ float csum[CSIZE];   // written cross-CTA into rank 0
    __shared__ int   ccnt[CSIZE];

    if (tid < PPC) pv[tid] = 0;
    __syncthreads();

    float acc = 0.0f;
    if (tid < LOADERS) {
        // 12 consecutive floats per thread = 3 float4 loads.
        // Base = (b*2176 + chunk*544)*3 floats -> 6528B-aligned chunks, 16B ok.
        const float4* __restrict__ g4 =
            (const float4*)(gts + ((size_t)b * PD + chunk * EPC) * 3) +
            (size_t)tid * 3;
        const float* __restrict__ pr = preds + (size_t)b * L;

        float4 a0 = g4[0];
        float4 a1 = g4[1];
        float4 a2 = g4[2];

        float vals[4] = { a0.x, a0.w, a1.z, a2.y };
        float fidx[4] = { a0.y, a1.x, a1.w, a2.z };
        float flag[4] = { a0.z, a1.y, a2.x, a2.w };

        bool  v[4];
        float gat[4];
        #pragma unroll
        for (int i = 0; i < 4; i++) {
            v[i]   = flag[i] > 0.0f;
            gat[i] = v[i] ? __ldg(pr + (int)fidx[i]) : 0.0f;  // independent gathers
        }

        const int e0 = tid * 4;   // element index within chunk
        #pragma unroll
        for (int i = 0; i < 4; i++) {
            if (v[i]) {
                acc += fabsf(gat[i] - vals[i]);
                pv[(e0 + i) / D] = 1;   // benign race: all writers store 1
            }
        }
    }

    // intra-CTA reduce
    #pragma unroll
    for (int off = 16; off > 0; off >>= 1)
        acc += __shfl_xor_sync(0xFFFFFFFFu, acc, off);

    const int wid = tid >> 5;
    const int lid = tid & 31;
    if (lid == 0) wsum[wid] = acc;
    __syncthreads();

    if (tid == 0) {
        float total = 0.0f;
        #pragma unroll
        for (int w = 0; w < NW; w++) total += wsum[w];
        int cnt = 0;
        #pragma unroll
        for (int p = 0; p < PPC; p++) cnt += pv[p];

        // Push partials into cluster rank 0's SMEM slot [chunk].
        uint32_t s_local = (uint32_t)__cvta_generic_to_shared(&csum[chunk]);
        uint32_t c_local = (uint32_t)__cvta_generic_to_shared(&ccnt[chunk]);
        uint32_t s_r0, c_r0;
        asm("mapa.shared::cluster.u32 %0, %1, %2;" : "=r"(s_r0) : "r"(s_local), "r"(0));
        asm("mapa.shared::cluster.u32 %0, %1, %2;" : "=r"(c_r0) : "r"(c_local), "r"(0));
        asm volatile("st.shared::cluster.f32 [%0], %1;" :: "r"(s_r0), "f"(total) : "memory");
        asm volatile("st.shared::cluster.s32 [%0], %1;" :: "r"(c_r0), "r"(cnt)   : "memory");
    }

    // cluster barrier: release the DSMEM stores, acquire before rank-0 reads.
    asm volatile("barrier.cluster.arrive.aligned;" ::: "memory");
    asm volatile("barrier.cluster.wait.aligned;"   ::: "memory");

    if (chunk == 0 && tid == 0) {
        float s = csum[0] + csum[1] + csum[2] + csum[3];
        int   c = ccnt[0] + ccnt[1] + ccnt[2] + ccnt[3];
        out[b] = s / (float)c;
    }
}

extern "C" void kernel_launch(void* const* d_in, const int* in_sizes, int n_in,
                              void* d_out, int out_size)
{
    const float* preds = (const float*)d_in[0];
    const float* gts   = (const float*)d_in[1];
    float* out = (float*)d_out;
    regl1_kernel<<<B * CSIZE, TPC>>>(preds, gts, out);
}